// round 16
// baseline (speedup 1.0000x reference)
#include <cuda_runtime.h>
#include <math.h>

typedef unsigned long long ull;
#define BATCHN 8192
#define INDIM 512
#define PI_F 3.14159265358979323846f

// ---------- f32x2 packed primitives ----------
__device__ __forceinline__ ull pk(float x, float y) {
    ull r; asm("mov.b64 %0, {%1, %2};" : "=l"(r) : "f"(x), "f"(y)); return r;
}
__device__ __forceinline__ float2 upk(ull v) {
    float2 f; asm("mov.b64 {%0, %1}, %2;" : "=f"(f.x), "=f"(f.y) : "l"(v)); return f;
}
__device__ __forceinline__ ull spl(float x) { return pk(x, x); }
__device__ __forceinline__ ull f2fma(ull a, ull b, ull c) {
    ull d; asm("fma.rn.f32x2 %0, %1, %2, %3;" : "=l"(d) : "l"(a), "l"(b), "l"(c)); return d;
}
__device__ __forceinline__ ull f2mul(ull a, ull b) {
    ull d; asm("mul.rn.f32x2 %0, %1, %2;" : "=l"(d) : "l"(a), "l"(b)); return d;
}
__device__ __forceinline__ ull f2add(ull a, ull b) {
    ull d; asm("add.rn.f32x2 %0, %1, %2;" : "=l"(d) : "l"(a), "l"(b)); return d;
}
__device__ __forceinline__ ull shx64(ull v, int m) {
    float2 f = upk(v);
    f.x = __shfl_xor_sync(0xffffffffu, f.x, m);
    f.y = __shfl_xor_sync(0xffffffffu, f.y, m);
    return pk(f.x, f.y);
}
__device__ __forceinline__ ull hswap(ull v) {
    float2 f = upk(v); return pk(f.y, f.x);
}
__device__ __forceinline__ float2 cmul(float2 a, float2 b) {
    return make_float2(a.x * b.x - a.y * b.y, a.x * b.y + a.y * b.x);
}

// coefficient set per gate. Fields (as ulonglong2 pairs):
// CMr, CMi, nCMi, COr, nCOr, COi, nCOi, pad
// CMi/nCMi/COr/nCOr are half-aware when the parity row includes the half bit (a0=1).
struct __align__(16) GateSplats { ull CMr, CMi, nCMi, COr, nCOr, COi, nCOi, pad; };

// ======== layout (T=16) ========
// stored index p[7:0]: p7..p4 = lane s3..s0, p3..p1 = pack j2..j0, p0 = half h.
// Initially (product state) logical bit k lives at p_k (wire w <-> bit 7-w).
// CNOT rings are linear maps; instead of moving data we track L with st[p]=psi[L p].
// After ring1: L1; after ring2: L2 = pi2*L1 (derived by hand, verified):
//   L1 rows (k7..k0):   0x7F,0xC0,0xE0,0xF0,0xF8,0xFC,0xFE,0xFF
//   L1^-1 col masks m_k: k7:0xC0 k6:0x60 k5:0x30 k4:0x18 k3:0x0C k2:0x06 k1:0x03 k0:0xC1
//   L2 rows (k7..k0):   0xE6,0xF3,0x9F,0x30,0x67,0xCC,0x99,0x33
//   L2^-1 col masks m_k: k7:0xF0 k6:0x78 k5:0x3C k4:0x1E k3:0x0F k2:0xC7 k1:0xF3 k0:0xB9
// Gate on wire w (bit k=7-w): partner p^m_k, side = parity(p & row_k(L)).
// Mask split: bits7..4 -> shfl LM, bits3..1 -> pack JM, bit0 -> half flip HF.
// Parity split: AL = lane part (bits7..4), AP = pack/half part (bits3..0).

template<int LM, int JM, int HF, int AL, int AP>
__device__ __forceinline__ void gateU(ull R[8], ull I[8], unsigned lane, const GateSplats* gp) {
    const ulonglong2* q = reinterpret_cast<const ulonglong2*>(gp);
    ulonglong2 q0 = q[0], q1 = q[1], q2 = q[2], q3 = q[3];
    ull CMr = q0.x, CMi = q0.y, nCMi = q1.x, COr = q1.y;
    ull nCOr = q2.x, COi = q2.y, nCOi = q3.x;
    bool pl = (__popc((int)(lane & AL)) & 1) != 0;
    // set A: packs with compile-time parity 0 (side = pl); set B: opposite
    ull CMiA  = pl ? nCMi : CMi,  nCMiA = pl ? CMi  : nCMi, COrA = pl ? nCOr : COr;
    ull CMiB  = pl ? CMi  : nCMi, nCMiB = pl ? nCMi : CMi,  COrB = pl ? COr  : nCOr;

    if (JM == 0) {
        #pragma unroll
        for (int j = 0; j < 8; j++) {
            const int cp = __popc((j << 1) & AP) & 1;
            ull cmi = cp ? CMiB : CMiA, ncmi = cp ? nCMiB : nCMiA, cor = cp ? COrB : COrA;
            ull oR = R[j], oI = I[j];
            if (LM) { oR = shx64(oR, LM); oI = shx64(oI, LM); }
            if (HF) { oR = hswap(oR); oI = hswap(oI); }
            ull sR = R[j], sI = I[j];
            R[j] = f2fma(CMr, sR, f2fma(ncmi, sI, f2fma(cor, oR, f2mul(nCOi, oI))));
            I[j] = f2fma(CMr, sI, f2fma(cmi, sR, f2fma(cor, oI, f2mul(COi, oR))));
        }
    } else {
        const int HB = JM & (-JM);
        #pragma unroll
        for (int j = 0; j < 8; j++) {
            if ((j & HB) == 0) {
                const int jp = j ^ JM;
                const int cp1 = __popc((j << 1) & AP) & 1;
                const int cp2 = __popc((jp << 1) & AP) & 1;
                ull cmi1 = cp1 ? CMiB : CMiA, ncmi1 = cp1 ? nCMiB : nCMiA, cor1 = cp1 ? COrB : COrA;
                ull cmi2 = cp2 ? CMiB : CMiA, ncmi2 = cp2 ? nCMiB : nCMiA, cor2 = cp2 ? COrB : COrA;
                ull o1R = R[jp], o1I = I[jp], o2R = R[j], o2I = I[j];
                if (LM) {
                    o1R = shx64(o1R, LM); o1I = shx64(o1I, LM);
                    o2R = shx64(o2R, LM); o2I = shx64(o2I, LM);
                }
                if (HF) {
                    o1R = hswap(o1R); o1I = hswap(o1I);
                    o2R = hswap(o2R); o2I = hswap(o2I);
                }
                ull s1R = R[j], s1I = I[j], s2R = R[jp], s2I = I[jp];
                R[j]  = f2fma(CMr, s1R, f2fma(ncmi1, s1I, f2fma(cor1, o1R, f2mul(nCOi, o1I))));
                I[j]  = f2fma(CMr, s1I, f2fma(cmi1,  s1R, f2fma(cor1, o1I, f2mul(COi,  o1R))));
                R[jp] = f2fma(CMr, s2R, f2fma(ncmi2, s2I, f2fma(cor2, o2R, f2mul(nCOi, o2I))));
                I[jp] = f2fma(CMr, s2I, f2fma(cmi2,  s2R, f2fma(cor2, o2I, f2mul(COi,  o2R))));
            }
        }
    }
}

__global__ __launch_bounds__(128, 6) void qlayer_kernel(
    const float* __restrict__ x,
    const float* __restrict__ W,
    const float* __restrict__ bvec,
    const float* __restrict__ scale,
    const float* __restrict__ bias,
    const float* __restrict__ qw,
    float* __restrict__ out)
{
    __shared__ float sW[8][512];          // 16 KB
    __shared__ GateSplats sSp[2][8];      // layers 1,2 coefficient sets
    __shared__ float2 sG0[8][4];          // layer-0 raw Rot matrices
    __shared__ uint4 sPv[16];             // 256 final-sign bytes
    __shared__ float sPar[24];            // bvec | scale | bias

    const int tid = threadIdx.x;

    for (int i = tid; i < 1024; i += 128)
        ((float4*)sW)[i] = ((const float4*)W)[i];

    if (tid < 24) {
        sPar[tid] = (tid < 8) ? bvec[tid] : (tid < 16) ? scale[tid - 8] : bias[tid - 16];
        int l = tid >> 3, w = tid & 7;
        const float* qp = qw + (l * 8 + w) * 3;
        float phi = qp[0], th = qp[1], om = qp[2];
        float ct, st_; sincosf(0.5f * th, &st_, &ct);
        float c0, s0, c1, s1;
        sincosf(0.5f * (phi + om), &s0, &c0);
        sincosf(0.5f * (phi - om), &s1, &c1);
        float2 u00 = make_float2(ct * c0, -ct * s0);
        float2 u01 = make_float2(-st_ * c1, -st_ * s1);
        if (l == 0) {
            sG0[w][0] = u00;
            sG0[w][1] = u01;
            sG0[w][2] = make_float2(st_ * c1, -st_ * s1);  // u10
            sG0[w][3] = make_float2(ct * c0, ct * s0);     // u11
        } else {
            // a0 = half-bit-in-parity flag per gate: L1 mask 0x81, L2 mask 0xD6
            int a0 = (((l == 1) ? 0x81 : 0xD6) >> w) & 1;
            float cmi0 = u00.y, cor0 = u01.x, coi = u01.y;
            GateSplats& g = sSp[l - 1][w];
            g.CMr  = spl(u00.x);
            g.CMi  = pk( cmi0, a0 ? -cmi0 :  cmi0);
            g.nCMi = pk(-cmi0, a0 ?  cmi0 : -cmi0);
            g.COr  = pk( cor0, a0 ? -cor0 :  cor0);
            g.nCOr = pk(-cor0, a0 ?  cor0 : -cor0);
            g.COi  = spl(coi);
            g.nCOi = spl(-coi);
            g.pad  = 0;
        }
    }
    // final sign table: logical-pre-ring3 index lp = L2 * p, then ring3 forward map.
    for (int i = tid; i < 256; i += 128) {
        const int l2r[8] = {0x33, 0x99, 0xCC, 0x67, 0x30, 0x9F, 0xF3, 0xE6}; // row k of L2
        int lp = 0;
        #pragma unroll
        for (int k = 0; k < 8; k++)
            lp |= (__popc(i & l2r[k]) & 1) << k;
        #pragma unroll
        for (int w = 0; w < 8; w++) {
            int c = 7 - w, t = 7 - ((w + 3) & 7);
            if ((lp >> c) & 1) lp ^= (1 << t);
        }
        ((unsigned char*)sPv)[i] = (unsigned char)lp;
    }
    __syncthreads();

    const unsigned lane = tid & 31;
    const unsigned s = lane & 15;
    const int b = blockIdx.x * 8 + (tid >> 5) * 2 + (lane >> 4);

    // ---- projection ----
    float acc[8];
    #pragma unroll
    for (int w = 0; w < 8; w++) acc[w] = 0.f;
    const float4* xr = (const float4*)(x + (size_t)b * INDIM);
    #pragma unroll
    for (int c = 0; c < 8; c++) {
        float4 xv = xr[(c << 4) + s];
        #pragma unroll
        for (int w = 0; w < 8; w++) {
            float4 wv = ((const float4*)(sW[w]))[(c << 4) + s];
            acc[w] += xv.x * wv.x + xv.y * wv.y + xv.z * wv.z + xv.w * wv.w;
        }
    }
    {
        ull pa[4];
        #pragma unroll
        for (int t = 0; t < 4; t++) pa[t] = pk(acc[2 * t], acc[2 * t + 1]);
        #pragma unroll
        for (int off = 8; off > 0; off >>= 1) {
            #pragma unroll
            for (int t = 0; t < 4; t++) pa[t] = f2add(pa[t], shx64(pa[t], off));
        }
        #pragma unroll
        for (int t = 0; t < 4; t++) { float2 f = upk(pa[t]); acc[2 * t] = f.x; acc[2 * t + 1] = f.y; }
    }

    // ---- angles + fold layer-0 Rot ----
    float2 wa[8], wb[8];
    #pragma unroll
    for (int w = 0; w < 8; w++) {
        float t = (acc[w] + sPar[w]) * sPar[8 + w] + sPar[16 + w];
        float sg = 1.f / (1.f + __expf(-t));
        float cc, ss;
        __sincosf(sg * (0.5f * PI_F), &ss, &cc);
        float2 g00 = sG0[w][0], g01 = sG0[w][1];
        float2 g10 = sG0[w][2], g11 = sG0[w][3];
        wa[w] = make_float2(fmaf(g00.x, cc, g01.x * ss), fmaf(g00.y, cc, g01.y * ss));
        wb[w] = make_float2(fmaf(g10.x, cc, g11.x * ss), fmaf(g10.y, cc, g11.y * ss));
    }

    // ---- build product state (L0 = I; ring1 is pure relabeling => stored array IS psi0) ----
    float2 A = (s & 8) ? wb[0] : wa[0];
    A = cmul(A, (s & 4) ? wb[1] : wa[1]);
    A = cmul(A, (s & 2) ? wb[2] : wa[2]);
    A = cmul(A, (s & 1) ? wb[3] : wa[3]);

    float2 t4a = cmul(A, wa[4]), t4b = cmul(A, wb[4]);
    float2 t5[4];
    t5[0] = cmul(t4a, wa[5]); t5[1] = cmul(t4a, wb[5]);
    t5[2] = cmul(t4b, wa[5]); t5[3] = cmul(t4b, wb[5]);

    ull W7r  = pk(wa[7].x, wb[7].x);
    ull W7i  = pk(wa[7].y, wb[7].y);
    ull nW7i = pk(-wa[7].y, -wb[7].y);

    ull R[8], I[8];
    #pragma unroll
    for (int j = 0; j < 8; j++) {
        float2 C = cmul(t5[j >> 1], (j & 1) ? wb[6] : wa[6]);
        ull Cre = spl(C.x), Cim = spl(C.y);
        R[j] = f2fma(Cre, W7r, f2mul(Cim, nW7i));
        I[j] = f2fma(Cre, W7i, f2mul(Cim, W7r));
    }

    // ---- layer-1 Rots (ring1 folded into masks via L1) ----
    gateU<12, 0, 0,  7, 0xF>(R, I, lane, &sSp[0][0]);   // wire0 k7 m=0xC0 a=0x7F
    gateU< 6, 0, 0, 12, 0x0>(R, I, lane, &sSp[0][1]);   // wire1 k6 m=0x60 a=0xC0
    gateU< 3, 0, 0, 14, 0x0>(R, I, lane, &sSp[0][2]);   // wire2 k5 m=0x30 a=0xE0
    gateU< 1, 4, 0, 15, 0x0>(R, I, lane, &sSp[0][3]);   // wire3 k4 m=0x18 a=0xF0
    gateU< 0, 6, 0, 15, 0x8>(R, I, lane, &sSp[0][4]);   // wire4 k3 m=0x0C a=0xF8
    gateU< 0, 3, 0, 15, 0xC>(R, I, lane, &sSp[0][5]);   // wire5 k2 m=0x06 a=0xFC
    gateU< 0, 1, 1, 15, 0xE>(R, I, lane, &sSp[0][6]);   // wire6 k1 m=0x03 a=0xFE
    gateU<12, 0, 1, 15, 0xF>(R, I, lane, &sSp[0][7]);   // wire7 k0 m=0xC1 a=0xFF

    // ---- layer-2 Rots (ring2 folded via L2) ----
    gateU<15, 0, 0, 14, 0x6>(R, I, lane, &sSp[1][0]);   // wire0 k7 m=0xF0 a=0xE6
    gateU< 7, 4, 0, 15, 0x3>(R, I, lane, &sSp[1][1]);   // wire1 k6 m=0x78 a=0xF3
    gateU< 3, 6, 0,  9, 0xF>(R, I, lane, &sSp[1][2]);   // wire2 k5 m=0x3C a=0x9F
    gateU< 1, 7, 0,  3, 0x0>(R, I, lane, &sSp[1][3]);   // wire3 k4 m=0x1E a=0x30
    gateU< 0, 7, 1,  6, 0x7>(R, I, lane, &sSp[1][4]);   // wire4 k3 m=0x0F a=0x67
    gateU<12, 3, 1, 12, 0xC>(R, I, lane, &sSp[1][5]);   // wire5 k2 m=0xC7 a=0xCC
    gateU<15, 1, 1,  9, 0x9>(R, I, lane, &sSp[1][6]);   // wire6 k1 m=0xF3 a=0x99
    gateU<11, 4, 1,  3, 0x3>(R, I, lane, &sSp[1][7]);   // wire7 k0 m=0xB9 a=0x33

    // ---- measurement: signs via F = pi3*L2 (sPv). Halves differ by F*e0 = 0x87
    //      -> wires {0,5,6,7} use dif, others sum. ----
    uint4 q0 = sPv[s];
    unsigned su[4] = {q0.x, q0.y, q0.z, q0.w};

    float zs[8];
    #pragma unroll
    for (int w = 0; w < 8; w++) zs[w] = 0.f;
    #pragma unroll
    for (int j = 0; j < 8; j++) {
        ull P = f2fma(R[j], R[j], f2mul(I[j], I[j]));
        float2 pp = upk(P);
        float sum = pp.x + pp.y;
        float dif = pp.x - pp.y;
        unsigned s8 = (su[j >> 1] >> ((j & 1) * 16)) & 0xffu;  // sign byte of even amp (h=0)
        #pragma unroll
        for (int w = 0; w < 8; w++) {
            float val = (w == 0 || w >= 5) ? dif : sum;
            unsigned sm = (s8 << (24 + w)) & 0x80000000u;
            zs[w] += __int_as_float(__float_as_int(val) ^ sm);
        }
    }

    ull zp[4];
    #pragma unroll
    for (int t = 0; t < 4; t++) zp[t] = pk(zs[2 * t], zs[2 * t + 1]);
    #pragma unroll
    for (int off = 8; off > 0; off >>= 1) {
        #pragma unroll
        for (int t = 0; t < 4; t++) zp[t] = f2add(zp[t], shx64(zp[t], off));
    }
    float2 z01 = upk(zp[0]), z23 = upk(zp[1]), z45 = upk(zp[2]), z67 = upk(zp[3]);
    float v = z01.x;
    if (s == 1) v = z01.y;
    if (s == 2) v = z23.x;
    if (s == 3) v = z23.y;
    if (s == 4) v = z45.x;
    if (s == 5) v = z45.y;
    if (s == 6) v = z67.x;
    if (s == 7) v = z67.y;
    if (s < 8) out[(size_t)b * 8 + s] = v;
}

extern "C" void kernel_launch(void* const* d_in, const int* in_sizes, int n_in,
                              void* d_out, int out_size) {
    const float* x     = (const float*)d_in[0];
    const float* W     = (const float*)d_in[1];
    const float* bvec  = (const float*)d_in[2];
    const float* scale = (const float*)d_in[3];
    const float* bias  = (const float*)d_in[4];
    const float* qw    = (const float*)d_in[5];
    float* out = (float*)d_out;
    qlayer_kernel<<<BATCHN / 8, 128>>>(x, W, bvec, scale, bias, qw, out);
}